// round 9
// baseline (speedup 1.0000x reference)
#include <cuda_runtime.h>
#include <cstdint>

// Perfect 4-ary tree, depth 10. Level-t flags start at B_t = (4^t - 1)/3.
#define N_LEVEL9   262144      // 4^9
#define B7         5461
#define B8         21845
#define B9         87381
#define MAGIC      0x4B000000  // float bits of 2^23
#define TWO23      8388608.0f
// rev3 lookup packed as nibbles: nibble j = bit-reversal of 3-bit j
#define REV3T      0x73516240u

__device__ int g_R7[16384];    // reversed 21-bit codes of all level-7 nodes

// Build per-block LUT: tbl[f] = 4 x 3-bit rev3(set-bit positions of f),
// ascending bit order (rank r at bits [3r, 3r+2]). Requires blockDim >= 256.
__device__ __forceinline__ void build_rev3_rank_table(int* tbl) {
    const int tid = threadIdx.x;
    if (tid < 256) {
        unsigned m = (unsigned)tid | 0x100u;   // sentinel keeps lsb well-defined
        int packed = 0;
        #pragma unroll
        for (int r = 0; r < 4; ++r) {
            const int j = 31 - __clz(m & (0u - m));    // lsb position
            packed |= (int)((REV3T >> ((j & 7) << 2)) & 7u) << (3 * r);
            m &= m - 1;
        }
        tbl[tid] = packed;
    }
    __syncthreads();
}

// ---------------------------------------------------------------------------
// Kernel 1: one thread per level-7 node. All 7 flag loads are independent
// (indices are pure functions of p7), heavily broadcast across threads.
// ---------------------------------------------------------------------------
__global__ void __launch_bounds__(256)
build_R7_kernel(const int* __restrict__ flags) {
    __shared__ int tbl[256];
    build_rev3_rank_table(tbl);

    const int p7 = blockIdx.x * blockDim.x + threadIdx.x;   // 0..16383

    const int bases[7] = {0, 1, 5, 21, 85, 341, 1365};
    int R = 0;
    #pragma unroll
    for (int t = 0; t < 7; ++t) {
        const int node = p7 >> (2 * (7 - t));        // level-t node on path
        const int r    = (p7 >> (2 * (6 - t))) & 3;  // child rank taken
        const int f    = __ldg(&flags[bases[t] + node]) & 255;
        const int rj   = (tbl[f] >> (3 * r)) & 7;
        R |= rj << (3 * t);
    }
    g_R7[p7] = R;
}

// ---------------------------------------------------------------------------
// Kernel 2: one thread per level-9 node -> 4 leaves (12 floats, 3 STG.128).
// d0/d1 and the low 7 bits of d2 are shared across the thread's 4 leaves.
// int->float via magic-number OR + exact 2^23 subtraction (no I2F).
// ---------------------------------------------------------------------------
__global__ void __launch_bounds__(256)
decode_leaves_kernel(const int* __restrict__ flags,
                     const float* __restrict__ offset,
                     const float* __restrict__ scale,
                     float* __restrict__ out) {
    __shared__ int tbl[256];
    build_rev3_rank_table(tbl);

    const int p9 = blockIdx.x * blockDim.x + threadIdx.x;   // exact grid cover
    const int p8 = p9 >> 2;
    const int p7 = p9 >> 4;

    const int R7 = g_R7[p7];                                  // 16-way broadcast
    const int f7 = __ldg(&flags[B7 + p7]) & 255;
    const int f8 = __ldg(&flags[B8 + p8]) & 255;
    const int f9 = __ldg(&flags[B9 + p9]) & 255;              // coalesced

    const int rj7 = (tbl[f7] >> (3 * (p8 & 3))) & 7;          // broadcast LDS
    const int rj8 = (tbl[f8] >> (3 * (p9 & 3))) & 7;
    const int t9  = tbl[f9];                                  // random LDS

    // reversed 27-bit code of this level-9 node
    const int R9 = R7 | (rj7 << 21) | (rj8 << 24);

    const float s0 = __ldg(&scale[0]),  s1 = __ldg(&scale[1]),  s2 = __ldg(&scale[2]);
    const float o0 = __ldg(&offset[0]), o1 = __ldg(&offset[1]), o2 = __ldg(&offset[2]);

    // Fields shared by this thread's 4 leaves
    const int   b0 = (R9 & 1023) | MAGIC;
    const int   b1 = ((R9 >> 10) & 1023) | MAGIC;
    const float v0 = fmaf(__int_as_float(b0) - TWO23, s0, o0);
    const float v1 = fmaf(__int_as_float(b1) - TWO23, s1, o1);
    const int  c2M = MAGIC | (R9 >> 20);          // low 7 bits of d2 + magic

    // Per-leaf: only rev3(j9) (bits 7..9 of d2) varies
    float v2[4];
    #pragma unroll
    for (int r = 0; r < 4; ++r) {
        const int rj = (t9 >> (3 * r)) & 7;
        const float f2 = __int_as_float(c2M + (rj << 7)) - TWO23;   // exact
        v2[r] = fmaf(f2, s2, o2);
    }

    // 4 leaves x 3 floats = 48 contiguous bytes -> 3 aligned float4 stores
    float4* o4 = reinterpret_cast<float4*>(out) + (size_t)p9 * 3;
    o4[0] = make_float4(v0,    v1,    v2[0], v0);
    o4[1] = make_float4(v1,    v2[1], v0,    v1);
    o4[2] = make_float4(v2[2], v0,    v1,    v2[3]);
}

extern "C" void kernel_launch(void* const* d_in, const int* in_sizes, int n_in,
                              void* d_out, int out_size) {
    const int*   flags  = (const int*)d_in[0];
    const float* offset = (const float*)d_in[1];
    const float* scale  = (const float*)d_in[2];
    float*       out    = (float*)d_out;

    build_R7_kernel<<<16384 / 256, 256>>>(flags);
    decode_leaves_kernel<<<N_LEVEL9 / 256, 256>>>(flags, offset, scale, out);
}

// round 17
// speedup vs baseline: 1.2316x; 1.2316x over previous
#include <cuda_runtime.h>
#include <cstdint>

// Perfect 4-ary tree, depth 10. Level-t flags start at B_t = (4^t - 1)/3.
#define N_LEVEL9   262144      // 4^9 level-9 nodes (4 leaves each)
#define B7         5461
#define B8         21845
#define B9         87381
#define MAGIC      0x4B000000  // float bits of 2^23
#define TWO23      8388608.0f
// rev3 lookup packed as nibbles: nibble j = bit-reversal of 3-bit j
#define REV3T      0x73516240u

// Build per-block LUT: tbl[f] = 4 x 3-bit rev3(set-bit positions of f),
// ascending bit order (rank r at bits [3r, 3r+2]). Requires blockDim >= 256.
__device__ __forceinline__ void build_rev3_rank_table(int* tbl) {
    const int tid = threadIdx.x;
    if (tid < 256) {
        unsigned m = (unsigned)tid | 0x100u;   // sentinel keeps lsb well-defined
        int packed = 0;
        #pragma unroll
        for (int r = 0; r < 4; ++r) {
            const int j = 31 - __clz(m & (0u - m));    // lsb position
            packed |= (int)((REV3T >> ((j & 7) << 2)) & 7u) << (3 * r);
            m &= m - 1;
        }
        tbl[tid] = packed;
    }
    __syncthreads();
}

// ---------------------------------------------------------------------------
// Single fused kernel: one thread per level-9 node -> 4 leaves.
// The full 10-level path is recomputed per thread:
//   levels 0..6: broadcast LDGs (4^(9-t)-way shared across threads)
//   levels 7..9: f7 (16-way bcast), f8 (4-way bcast), f9 (coalesced)
// All 10 LDGs are independent -> high MLP in a latency-bound kernel.
// int->float via magic-number OR + exact 2^23 subtraction (no I2F).
// ---------------------------------------------------------------------------
__global__ void __launch_bounds__(256)
decode_fused_kernel(const int* __restrict__ flags,
                    const float* __restrict__ offset,
                    const float* __restrict__ scale,
                    float* __restrict__ out) {
    __shared__ int tbl[256];
    build_rev3_rank_table(tbl);

    const int p9 = blockIdx.x * blockDim.x + threadIdx.x;   // exact grid cover
    const int p8 = p9 >> 2;
    const int p7 = p9 >> 4;

    // Issue all flag loads up front (independent; compiler batches LDGs).
    const int bases[7] = {0, 1, 5, 21, 85, 341, 1365};
    int fu[7];
    #pragma unroll
    for (int t = 0; t < 7; ++t)
        fu[t] = __ldg(&flags[bases[t] + (p9 >> (2 * (9 - t)))]) & 255;
    const int f7 = __ldg(&flags[B7 + p7]) & 255;
    const int f8 = __ldg(&flags[B8 + p8]) & 255;
    const int f9 = __ldg(&flags[B9 + p9]) & 255;              // coalesced

    // Reversed prefix for levels 0..6
    int R = 0;
    #pragma unroll
    for (int t = 0; t < 7; ++t) {
        const int r = (p9 >> (2 * (8 - t))) & 3;    // child rank at level t
        R |= ((tbl[fu[t]] >> (3 * r)) & 7) << (3 * t);
    }

    const int rj7 = (tbl[f7] >> (3 * (p8 & 3))) & 7;
    const int rj8 = (tbl[f8] >> (3 * (p9 & 3))) & 7;
    const int t9  = tbl[f9];

    // reversed 27-bit code of this level-9 node
    const int R9 = R | (rj7 << 21) | (rj8 << 24);

    const float s0 = __ldg(&scale[0]),  s1 = __ldg(&scale[1]),  s2 = __ldg(&scale[2]);
    const float o0 = __ldg(&offset[0]), o1 = __ldg(&offset[1]), o2 = __ldg(&offset[2]);

    // Fields shared by this thread's 4 leaves
    const int   b0 = (R9 & 1023) | MAGIC;
    const int   b1 = ((R9 >> 10) & 1023) | MAGIC;
    const float v0 = fmaf(__int_as_float(b0) - TWO23, s0, o0);
    const float v1 = fmaf(__int_as_float(b1) - TWO23, s1, o1);
    const int  c2M = MAGIC | (R9 >> 20);          // low 7 bits of d2 + magic

    // Per-leaf: only rev3(j9) (bits 7..9 of d2) varies
    float v2[4];
    #pragma unroll
    for (int r = 0; r < 4; ++r) {
        const int rj = (t9 >> (3 * r)) & 7;
        const float f2 = __int_as_float(c2M + (rj << 7)) - TWO23;   // exact
        v2[r] = fmaf(f2, s2, o2);
    }

    // 4 leaves x 3 floats = 48 contiguous bytes -> 3 aligned float4 stores
    float4* o4 = reinterpret_cast<float4*>(out) + (size_t)p9 * 3;
    o4[0] = make_float4(v0,    v1,    v2[0], v0);
    o4[1] = make_float4(v1,    v2[1], v0,    v1);
    o4[2] = make_float4(v2[2], v0,    v1,    v2[3]);
}

extern "C" void kernel_launch(void* const* d_in, const int* in_sizes, int n_in,
                              void* d_out, int out_size) {
    const int*   flags  = (const int*)d_in[0];
    const float* offset = (const float*)d_in[1];
    const float* scale  = (const float*)d_in[2];
    float*       out    = (float*)d_out;

    decode_fused_kernel<<<N_LEVEL9 / 256, 256>>>(flags, offset, scale, out);
}